// round 12
// baseline (speedup 1.0000x reference)
#include <cuda_runtime.h>

// LSTMAnomalyDetector: B=4096, T=512, I=3, H=64 (PyTorch gate order i,f,g,o)
//
// Round-12: symmetric-tail warp-granular k-split.
// grid=256 x NT=256, RT=16 rows/CTA, 2 CTAs/SM -> 16 warps/SM.
// Matvec: threads 0-127 (kh=0) accumulate k in [0,32), threads 128-255 (kh=1)
// k in [32,64); every warp kh-uniform -> round-9 conflict-free smem pattern.
// Tail is SYMMETRIC: kh=0 owns rows 0-3 of its rg block, kh=1 owns rows 4-7;
// each half stores the partials it does not own, both halves combine + do
// nonlinearities on 4 cells each. bias + Wih*x(t+1) init and the decode of
// h(t-1) also run in the tail, feeding the fma/lsu pipes under the MUFU burst.

#define B_   4096
#define T_   512
#define H_   64
#define RT   16      // rows per CTA
#define NT   256     // threads per CTA
#define HPD  18      // hdup row pitch in ulls (16 used + pad)
#define KH   32      // k per half

typedef unsigned long long ull;

__device__ __forceinline__ float tanhfast(float x) {
    float y; asm("tanh.approx.f32 %0, %1;" : "=f"(y) : "f"(x)); return y;
}
__device__ __forceinline__ float sigf(float x) {
    return fmaf(0.5f, tanhfast(0.5f * x), 0.5f);
}
__device__ __forceinline__ ull pack2(float a, float b) {   // a -> low lane
    ull r; asm("mov.b64 %0, {%1, %2};" : "=l"(r) : "f"(a), "f"(b)); return r;
}
__device__ __forceinline__ void unpack2(ull v, float& lo, float& hi) {
    asm("mov.b64 {%0, %1}, %2;" : "=f"(lo), "=f"(hi) : "l"(v));
}
__device__ __forceinline__ ull fma2(ull a, ull b, ull c) {
    ull d; asm("fma.rn.f32x2 %0, %1, %2, %3;" : "=l"(d) : "l"(a), "l"(b), "l"(c)); return d;
}
__device__ __forceinline__ ull add2(ull a, ull b) {
    ull d; asm("add.rn.f32x2 %0, %1, %2;" : "=l"(d) : "l"(a), "l"(b)); return d;
}

struct Smem {
    ulonglong2 W4[H_][H_];      // 64KB [k][u]: .x=(wi,wf) .y=(wg,wo)
    ull hdup[2][H_][HPD];       // 18KB [buf][unit][row]: (h,h) duplicated
    ulonglong2 partA[4][128];   // 8KB  kh=1 -> kh=0 partials (rows 0..3)
    ulonglong2 partB[4][128];   // 8KB  kh=0 -> kh=1 partials (rows 4..7)
    ull xdup[2][3][RT];         // [buf][comp][row]: (x,x) duplicated
    float wdec[3][H_];
};
#define SMEM_BYTES ((int)sizeof(Smem))

extern __shared__ char smem_raw[];

__global__ void __launch_bounds__(NT, 2)
lstm_persistent_kernel(const float* __restrict__ x,      // [B, T, 3]
                       const float* __restrict__ Wih,    // [256, 3]
                       const float* __restrict__ Whh,    // [256, 64]
                       const float* __restrict__ bih,    // [256]
                       const float* __restrict__ bhh,    // [256]
                       const float* __restrict__ Wdec,   // [3, 64]
                       const float* __restrict__ bdec,   // [3]
                       float* __restrict__ out)          // [B, T, 3]
{
    Smem* S = (Smem*)smem_raw;
    const int tid  = threadIdx.x;
    const int row0 = blockIdx.x * RT;

    const int kh  = tid >> 7;       // k half: [32*kh, 32*kh+32)
    const int hid = tid & 127;      // id within half
    const int u   = hid >> 1;       // unit 0..63
    const int rg  = hid & 1;        // matvec rows 8rg .. 8rg+7

    // ---- setup -----------------------------------------------------------
    for (int idx = tid; idx < H_ * H_; idx += NT) {
        const int k = idx >> 6, uu = idx & 63;
        const float wi = Whh[(0 * H_ + uu) * H_ + k];
        const float wf = Whh[(1 * H_ + uu) * H_ + k];
        const float wg = Whh[(2 * H_ + uu) * H_ + k];
        const float wo = Whh[(3 * H_ + uu) * H_ + k];
        *(float4*)&S->W4[k][uu] = make_float4(wi, wf, wg, wo);
    }
    for (int i = tid; i < 2 * H_ * HPD; i += NT) ((ull*)S->hdup)[i] = 0ull;
    for (int i = tid; i < 3 * H_; i += NT) ((float*)S->wdec)[i] = Wdec[i];

    // kh=0 carries bias + W_ih (gate-packed)
    const ull bias_if = pack2(bih[u]        + bhh[u],
                              bih[H_ + u]   + bhh[H_ + u]);
    const ull bias_go = pack2(bih[2*H_ + u] + bhh[2*H_ + u],
                              bih[3*H_ + u] + bhh[3*H_ + u]);
    ull wih_if[3], wih_go[3];
#pragma unroll
    for (int i = 0; i < 3; i++) {
        wih_if[i] = pack2(Wih[u * 3 + i],          Wih[(H_ + u) * 3 + i]);
        wih_go[i] = pack2(Wih[(2*H_ + u) * 3 + i], Wih[(3*H_ + u) * 3 + i]);
    }

    // decode / x-staging roles: kh=1, hid 0..47 -> (comp o, row r)
    const int o_ = hid >> 4;        // 0..2
    const int r_ = hid & 15;        // 0..15
    const bool is_dec = (kh == 1) && (hid < 48);
    float bd = 0.0f;
    if (is_dec) {
        bd = bdec[o_];
        const float xv = x[((size_t)(row0 + r_) * T_ + 0) * 3 + o_];
        S->xdup[0][o_][r_] = pack2(xv, xv);
    }

    // cell state: kh=0 owns rows 8rg+0..3, kh=1 owns rows 8rg+4..7
    float c[4];
#pragma unroll
    for (int p = 0; p < 4; p++) c[p] = 0.0f;

    __syncthreads();

    // prologue: acc init for t=0 (kh=0: bias + Wih*x(0); kh=1: zero)
    ull aif[8], ago[8];
    if (kh == 0) {
#pragma unroll
        for (int j = 0; j < 8; j++) { aif[j] = bias_if; ago[j] = bias_go; }
#pragma unroll
        for (int i = 0; i < 3; i++) {
            const ulonglong2* xpp = (const ulonglong2*)&S->xdup[0][i][8 * rg];
#pragma unroll
            for (int q = 0; q < 4; q++) {
                const ulonglong2 xq = xpp[q];
                aif[2*q]   = fma2(xq.x, wih_if[i], aif[2*q]);
                ago[2*q]   = fma2(xq.x, wih_go[i], ago[2*q]);
                aif[2*q+1] = fma2(xq.y, wih_if[i], aif[2*q+1]);
                ago[2*q+1] = fma2(xq.y, wih_go[i], ago[2*q+1]);
            }
        }
    } else {
#pragma unroll
        for (int j = 0; j < 8; j++) { aif[j] = 0ull; ago[j] = 0ull; }
    }

    // ---- timestep loop -----------------------------------------------------
    for (int t = 0; t < T_; t++) {
        const int A = t & 1, Bb = A ^ 1;

        // x(t+1) prefetch (LDG latency hidden under the matvec)
        float xp = 0.0f;
        if (is_dec && (t + 1) < T_)
            xp = x[((size_t)(row0 + r_) * T_ + (t + 1)) * 3 + o_];

        // matvec over my 32 k's: per k, 5x LDS.128 + 16x fma2 (branch-free)
        {
            const ulonglong2* wp = &S->W4[KH * kh][u];       // stride H_ per k
            const ull* hp = &S->hdup[A][KH * kh][8 * rg];    // stride HPD per k
#pragma unroll 2
            for (int k = 0; k < KH; k++) {
                const ulonglong2 wv = *wp;
                const ulonglong2 h01 = *(const ulonglong2*)(hp + 0);
                const ulonglong2 h23 = *(const ulonglong2*)(hp + 2);
                const ulonglong2 h45 = *(const ulonglong2*)(hp + 4);
                const ulonglong2 h67 = *(const ulonglong2*)(hp + 6);
                aif[0] = fma2(h01.x, wv.x, aif[0]);
                ago[0] = fma2(h01.x, wv.y, ago[0]);
                aif[1] = fma2(h01.y, wv.x, aif[1]);
                ago[1] = fma2(h01.y, wv.y, ago[1]);
                aif[2] = fma2(h23.x, wv.x, aif[2]);
                ago[2] = fma2(h23.x, wv.y, ago[2]);
                aif[3] = fma2(h23.y, wv.x, aif[3]);
                ago[3] = fma2(h23.y, wv.y, ago[3]);
                aif[4] = fma2(h45.x, wv.x, aif[4]);
                ago[4] = fma2(h45.x, wv.y, ago[4]);
                aif[5] = fma2(h45.y, wv.x, aif[5]);
                ago[5] = fma2(h45.y, wv.y, ago[5]);
                aif[6] = fma2(h67.x, wv.x, aif[6]);
                ago[6] = fma2(h67.x, wv.y, ago[6]);
                aif[7] = fma2(h67.y, wv.x, aif[7]);
                ago[7] = fma2(h67.y, wv.y, ago[7]);
                wp += H_;
                hp += HPD;
            }
        }

        // store the partials for the rows this half does NOT own
        if (kh == 0) {
            ulonglong2 v;
            v.x = aif[4]; v.y = aif[5]; S->partB[0][hid] = v;
            v.x = aif[6]; v.y = aif[7]; S->partB[1][hid] = v;
            v.x = ago[4]; v.y = ago[5]; S->partB[2][hid] = v;
            v.x = ago[6]; v.y = ago[7]; S->partB[3][hid] = v;
        } else {
            ulonglong2 v;
            v.x = aif[0]; v.y = aif[1]; S->partA[0][hid] = v;
            v.x = aif[2]; v.y = aif[3]; S->partA[1][hid] = v;
            v.x = ago[0]; v.y = ago[1]; S->partA[2][hid] = v;
            v.x = ago[2]; v.y = ago[3]; S->partA[3][hid] = v;
            if (is_dec) S->xdup[Bb][o_][r_] = pack2(xp, xp);  // stage x(t+1)
        }

        __syncthreads();   // partials + x(t+1) visible; everyone done with hdup[A]

        // ---- symmetric tail ----
        ull m_if0, m_if1, m_go0, m_go1;    // my 4 owned rows, gate-packed pairs
        if (kh == 0) {
            ulonglong2 p;
            p = S->partA[0][hid]; m_if0 = add2(aif[0], p.x); m_if1 = add2(aif[1], p.y);
            p = S->partA[1][hid]; ull m_if2 = add2(aif[2], p.x), m_if3 = add2(aif[3], p.y);
            ulonglong2 q0 = S->partA[2][hid];
            m_go0 = add2(ago[0], q0.x); m_go1 = add2(ago[1], q0.y);
            ulonglong2 q1 = S->partA[3][hid];
            ull m_go2 = add2(ago[2], q1.x), m_go3 = add2(ago[3], q1.y);

            float hout[4];
            {
                float gi, gf, gg, go;
                unpack2(m_if0, gi, gf); unpack2(m_go0, gg, go);
                float ig = sigf(gi), fg = sigf(gf), gt = tanhfast(gg), og = sigf(go);
                float cn = fmaf(fg, c[0], ig * gt); c[0] = cn; hout[0] = og * tanhfast(cn);
                unpack2(m_if1, gi, gf); unpack2(m_go1, gg, go);
                ig = sigf(gi); fg = sigf(gf); gt = tanhfast(gg); og = sigf(go);
                cn = fmaf(fg, c[1], ig * gt); c[1] = cn; hout[1] = og * tanhfast(cn);
                unpack2(m_if2, gi, gf); unpack2(m_go2, gg, go);
                ig = sigf(gi); fg = sigf(gf); gt = tanhfast(gg); og = sigf(go);
                cn = fmaf(fg, c[2], ig * gt); c[2] = cn; hout[2] = og * tanhfast(cn);
                unpack2(m_if3, gi, gf); unpack2(m_go3, gg, go);
                ig = sigf(gi); fg = sigf(gf); gt = tanhfast(gg); og = sigf(go);
                cn = fmaf(fg, c[3], ig * gt); c[3] = cn; hout[3] = og * tanhfast(cn);
            }
            ull* hd = &S->hdup[Bb][u][8 * rg];
            ulonglong2 v2;
            v2.x = pack2(hout[0], hout[0]); v2.y = pack2(hout[1], hout[1]);
            *(ulonglong2*)(hd + 0) = v2;
            v2.x = pack2(hout[2], hout[2]); v2.y = pack2(hout[3], hout[3]);
            *(ulonglong2*)(hd + 2) = v2;

            // re-init accumulators for step t+1: bias + Wih * x(t+1)
#pragma unroll
            for (int j = 0; j < 8; j++) { aif[j] = bias_if; ago[j] = bias_go; }
#pragma unroll
            for (int i = 0; i < 3; i++) {
                const ulonglong2* xpp = (const ulonglong2*)&S->xdup[Bb][i][8 * rg];
#pragma unroll
                for (int q = 0; q < 4; q++) {
                    const ulonglong2 xq = xpp[q];
                    aif[2*q]   = fma2(xq.x, wih_if[i], aif[2*q]);
                    ago[2*q]   = fma2(xq.x, wih_go[i], ago[2*q]);
                    aif[2*q+1] = fma2(xq.y, wih_if[i], aif[2*q+1]);
                    ago[2*q+1] = fma2(xq.y, wih_go[i], ago[2*q+1]);
                }
            }
        } else {
            ulonglong2 p;
            p = S->partB[0][hid]; m_if0 = add2(aif[4], p.x); m_if1 = add2(aif[5], p.y);
            p = S->partB[1][hid]; ull m_if2 = add2(aif[6], p.x), m_if3 = add2(aif[7], p.y);
            ulonglong2 q0 = S->partB[2][hid];
            m_go0 = add2(ago[4], q0.x); m_go1 = add2(ago[5], q0.y);
            ulonglong2 q1 = S->partB[3][hid];
            ull m_go2 = add2(ago[6], q1.x), m_go3 = add2(ago[7], q1.y);

            float hout[4];
            {
                float gi, gf, gg, go;
                unpack2(m_if0, gi, gf); unpack2(m_go0, gg, go);
                float ig = sigf(gi), fg = sigf(gf), gt = tanhfast(gg), og = sigf(go);
                float cn = fmaf(fg, c[0], ig * gt); c[0] = cn; hout[0] = og * tanhfast(cn);
                unpack2(m_if1, gi, gf); unpack2(m_go1, gg, go);
                ig = sigf(gi); fg = sigf(gf); gt = tanhfast(gg); og = sigf(go);
                cn = fmaf(fg, c[1], ig * gt); c[1] = cn; hout[1] = og * tanhfast(cn);
                unpack2(m_if2, gi, gf); unpack2(m_go2, gg, go);
                ig = sigf(gi); fg = sigf(gf); gt = tanhfast(gg); og = sigf(go);
                cn = fmaf(fg, c[2], ig * gt); c[2] = cn; hout[2] = og * tanhfast(cn);
                unpack2(m_if3, gi, gf); unpack2(m_go3, gg, go);
                ig = sigf(gi); fg = sigf(gf); gt = tanhfast(gg); og = sigf(go);
                cn = fmaf(fg, c[3], ig * gt); c[3] = cn; hout[3] = og * tanhfast(cn);
            }
            ull* hd = &S->hdup[Bb][u][8 * rg];
            ulonglong2 v2;
            v2.x = pack2(hout[0], hout[0]); v2.y = pack2(hout[1], hout[1]);
            *(ulonglong2*)(hd + 4) = v2;
            v2.x = pack2(hout[2], hout[2]); v2.y = pack2(hout[3], hout[3]);
            *(ulonglong2*)(hd + 6) = v2;

            // zero accumulators for step t+1
#pragma unroll
            for (int j = 0; j < 8; j++) { aif[j] = 0ull; ago[j] = 0ull; }

            // decode h(t-1) -> out[., t-1, .]  (hdup[A] untouched until next tail)
            if (is_dec && t > 0) {
                const float* hp_ = (const float*)&S->hdup[A][0][r_];
                const float* wd  = &S->wdec[o_][0];
                float s0 = 0.f, s1 = 0.f, s2 = 0.f, s3 = 0.f;
#pragma unroll 4
                for (int k = 0; k < H_; k += 4) {
                    s0 = fmaf(hp_[(k + 0) * (2 * HPD)], wd[k + 0], s0);
                    s1 = fmaf(hp_[(k + 1) * (2 * HPD)], wd[k + 1], s1);
                    s2 = fmaf(hp_[(k + 2) * (2 * HPD)], wd[k + 2], s2);
                    s3 = fmaf(hp_[(k + 3) * (2 * HPD)], wd[k + 3], s3);
                }
                out[((size_t)(row0 + r_) * T_ + (t - 1)) * 3 + o_] = (s0 + s1) + (s2 + s3) + bd;
            }
        }

        __syncthreads();   // h(t) + fresh accs ready for step t+1
    }

    // epilogue: out[T-2] was decoded in tail(T-1)? No: tail(t) decodes t-1, so
    // the last decoded index is T-2... tail(511) decodes out[510]. Decode both
    // remaining: out[511] from hdup[0] (h(511) stored in tail(511) -> Bb=0).
    if (is_dec) {
        const float* hp_ = (const float*)&S->hdup[0][0][r_];
        const float* wd  = &S->wdec[o_][0];
        float s0 = 0.f, s1 = 0.f, s2 = 0.f, s3 = 0.f;
#pragma unroll 4
        for (int k = 0; k < H_; k += 4) {
            s0 = fmaf(hp_[(k + 0) * (2 * HPD)], wd[k + 0], s0);
            s1 = fmaf(hp_[(k + 1) * (2 * HPD)], wd[k + 1], s1);
            s2 = fmaf(hp_[(k + 2) * (2 * HPD)], wd[k + 2], s2);
            s3 = fmaf(hp_[(k + 3) * (2 * HPD)], wd[k + 3], s3);
        }
        out[((size_t)(row0 + r_) * T_ + (T_ - 1)) * 3 + o_] = (s0 + s1) + (s2 + s3) + bd;
    }
}

extern "C" void kernel_launch(void* const* d_in, const int* in_sizes, int n_in,
                              void* d_out, int out_size) {
    const float* x    = (const float*)d_in[0];
    const float* Wih  = (const float*)d_in[1];
    const float* Whh  = (const float*)d_in[2];
    const float* bih  = (const float*)d_in[3];
    const float* bhh  = (const float*)d_in[4];
    const float* Wdec = (const float*)d_in[5];
    const float* bdec = (const float*)d_in[6];
    float* out = (float*)d_out;

    cudaFuncSetAttribute(lstm_persistent_kernel,
                         cudaFuncAttributeMaxDynamicSharedMemorySize, SMEM_BYTES);
    lstm_persistent_kernel<<<B_ / RT, NT, SMEM_BYTES>>>(x, Wih, Whh, bih, bhh, Wdec, bdec, out);
}

// round 14
// speedup vs baseline: 4.3410x; 4.3410x over previous
#include <cuda_runtime.h>
#include <cuda_fp16.h>
#include <cstdint>

// LSTMAnomalyDetector: B=4096, T=512, I=3, H=64 (PyTorch gate order i,f,g,o)
//
// Round-14: warp-level HMMA (mma.sync.m16n8k16 fp16->fp32; baseline PTX, works
// on plain sm_103 target -- tcgen05 is sm_103a-only and the harness targets sm_103).
// grid=128 CTAs x 256 threads, 32 batch rows/CTA, persistent over all 512 steps.
//
// Per step: gates[32,256] = A[32,80] @ B^T where A=[h | x | 1] fp16 SMEM tile
// (pitch 88 halfs -> ldmatrix conflict-free), B=[Whh | Wih | bias] in REGISTERS
// (loaded once). 8 warps x 8 MN tiles x 5 K-tiles = 40 HMMA/warp/step.
// N-tiles gate-aligned so each thread holds i,f,g,o for the same (row,unit):
// nonlinearities fully in-register, c fp32 in regs, h written back fp16.
// Decode (3 outputs) done SIMT in phase 1 (reads h(t-1) tile), overlapped.

#define B_    4096
#define T_    512
#define RT    32          // rows per CTA
#define NT    256
#define PH    88          // A-tile pitch in halfs (176B): 12r mod 32 distinct
#define PHB   176

typedef unsigned long long u64t;

__device__ __forceinline__ float tanhfast(float v) {
    float y; asm("tanh.approx.f32 %0, %1;" : "=f"(y) : "f"(v)); return y;
}
__device__ __forceinline__ float sigf(float v) {
    return fmaf(0.5f, tanhfast(0.5f * v), 0.5f);
}
__device__ __forceinline__ uint32_t smem_u32(const void* p) {
    uint32_t a;
    asm("{ .reg .u64 t; cvta.to.shared.u64 t, %1; cvt.u32.u64 %0, t; }" : "=r"(a) : "l"(p));
    return a;
}
__device__ __forceinline__ uint32_t h2u(float a, float b) {
    __half2 h = __floats2half2_rn(a, b);
    return *(uint32_t*)&h;
}
__device__ __forceinline__ void ldm4(uint32_t* r, uint32_t addr) {
    asm volatile("ldmatrix.sync.aligned.m8n8.x4.shared.b16 {%0,%1,%2,%3}, [%4];"
                 : "=r"(r[0]), "=r"(r[1]), "=r"(r[2]), "=r"(r[3]) : "r"(addr));
}
// d = a*b + 0
__device__ __forceinline__ void mma_z(float* d, const uint32_t* a, const uint32_t* b) {
    const float z = 0.0f;
    asm volatile("mma.sync.aligned.m16n8k16.row.col.f32.f16.f16.f32 "
                 "{%0,%1,%2,%3}, {%4,%5,%6,%7}, {%8,%9}, {%10,%10,%10,%10};"
                 : "=f"(d[0]), "=f"(d[1]), "=f"(d[2]), "=f"(d[3])
                 : "r"(a[0]), "r"(a[1]), "r"(a[2]), "r"(a[3]),
                   "r"(b[0]), "r"(b[1]), "f"(z));
}
// d += a*b
__device__ __forceinline__ void mma_acc(float* d, const uint32_t* a, const uint32_t* b) {
    asm volatile("mma.sync.aligned.m16n8k16.row.col.f32.f16.f16.f32 "
                 "{%0,%1,%2,%3}, {%4,%5,%6,%7}, {%8,%9}, {%0,%1,%2,%3};"
                 : "+f"(d[0]), "+f"(d[1]), "+f"(d[2]), "+f"(d[3])
                 : "r"(a[0]), "r"(a[1]), "r"(a[2]), "r"(a[3]),
                   "r"(b[0]), "r"(b[1]));
}

__global__ void __launch_bounds__(NT)
lstm_hmma_kernel(const float* __restrict__ x,      // [B, T, 3]
                 const float* __restrict__ Wih,    // [256, 3]
                 const float* __restrict__ Whh,    // [256, 64]
                 const float* __restrict__ bih,    // [256]
                 const float* __restrict__ bhh,    // [256]
                 const float* __restrict__ Wdec,   // [3, 64]
                 const float* __restrict__ bdec,   // [3]
                 float* __restrict__ out)          // [B, T, 3]
{
    __shared__ __align__(16) __half At[RT * PH];   // [row][col]: 0-63 h, 64-66 x, 67=1, 68-87 pad=0
    __shared__ float wdecs[3 * 64];

    const int tid  = threadIdx.x;
    const int wid  = tid >> 5;
    const int lane = tid & 31;
    const int row0 = blockIdx.x * RT;
    const int mt   = wid >> 2;     // M-tile (rows 16mt..16mt+15)
    const int sq   = wid & 3;      // set quad: sets {2sq, 2sq+1}

    // ---- setup -----------------------------------------------------------
    for (int i = tid; i < RT * (PH / 2); i += NT) ((uint32_t*)At)[i] = 0u;
    for (int i = tid; i < 192; i += NT) wdecs[i] = Wdec[i];
    __syncthreads();
    if (tid < 96) {   // x(0)
        const int o = tid >> 5, r = tid & 31;
        At[r * PH + 64 + o] = __float2half_rn(x[((size_t)(row0 + r) * T_) * 3 + o]);
    }
    if (tid < RT) At[tid * PH + 67] = __float2half_rn(1.0f);

    // B fragments in registers: [set_in_quad][gate][ktile][2]
    // B col n = global gate column = 64g + 8s + lane/4 (== Whh row index).
    uint32_t bF[2][4][5][2];
#pragma unroll
    for (int si = 0; si < 2; si++) {
        const int s = 2 * sq + si;
#pragma unroll
        for (int g = 0; g < 4; g++) {
            const int col = 64 * g + 8 * s + (lane >> 2);
            const int kq  = (lane & 3) * 2;
#pragma unroll
            for (int kt = 0; kt < 4; kt++) {
                const int k0 = 16 * kt + kq;
                bF[si][g][kt][0] = h2u(Whh[col * 64 + k0],     Whh[col * 64 + k0 + 1]);
                bF[si][g][kt][1] = h2u(Whh[col * 64 + k0 + 8], Whh[col * 64 + k0 + 9]);
            }
            // ktile 4: rows 64-66 = Wih, row 67 = bias, 68-79 = 0
            float va = 0.f, vb = 0.f;
            if (kq == 0)      { va = Wih[col * 3 + 0]; vb = Wih[col * 3 + 1]; }
            else if (kq == 2) { va = Wih[col * 3 + 2]; vb = bih[col] + bhh[col]; }
            bF[si][g][4][0] = h2u(va, vb);
            bF[si][g][4][1] = 0u;
        }
    }

    float c_[8];
#pragma unroll
    for (int j = 0; j < 8; j++) c_[j] = 0.0f;

    float bdv = 0.0f;
    if (tid < 96) bdv = bdec[tid >> 5];

    // ldmatrix A address (per lane), ktile via +32B
    const uint32_t abase = smem_u32(At)
        + (uint32_t)((16 * mt + (lane & 7) + ((lane >> 3) & 1) * 8) * PHB)
        + (uint32_t)(((lane >> 4) & 1) * 16);

    __syncthreads();

    // ---- timestep loop -----------------------------------------------------
    for (int t = 0; t < T_; t++) {
        // phase 1: load A fragments; decode h(t-1); prefetch x(t+1)
        uint32_t aF[5][4];
#pragma unroll
        for (int kt = 0; kt < 5; kt++) ldm4(aF[kt], abase + 32u * kt);

        float xr = 0.0f;
        if (tid < 96) {
            const int o = tid >> 5, r = tid & 31;
            if (t + 1 < T_)
                xr = x[((size_t)(row0 + r) * T_ + (t + 1)) * 3 + o];
            if (t > 0) {
                const uint32_t* hrow = (const uint32_t*)(At + r * PH);
                float dsum = bdv;
#pragma unroll 8
                for (int k2 = 0; k2 < 32; k2++) {
                    const float2 hv = __half22float2(*(const __half2*)&hrow[k2]);
                    dsum = fmaf(hv.x, wdecs[o * 64 + 2 * k2],     dsum);
                    dsum = fmaf(hv.y, wdecs[o * 64 + 2 * k2 + 1], dsum);
                }
                out[((size_t)(row0 + r) * T_ + (t - 1)) * 3 + o] = dsum;
            }
        }
        __syncthreads();   // all A frags loaded, decode done -> tile writable

        // phase 2: HMMA
        float acc[2][4][4];
#pragma unroll
        for (int si = 0; si < 2; si++)
#pragma unroll
            for (int g = 0; g < 4; g++) {
                mma_z(acc[si][g], aF[0], bF[si][g][0]);
#pragma unroll
                for (int kt = 1; kt < 5; kt++)
                    mma_acc(acc[si][g], aF[kt], bF[si][g][kt]);
            }

        // nonlinearities + h writeback (acc j: 0=(ra,u0) 1=(ra,u1) 2=(rb,u0) 3=(rb,u1))
        const int ra = 16 * mt + (lane >> 2);
#pragma unroll
        for (int si = 0; si < 2; si++) {
            const int u0 = 16 * sq + 8 * si + (lane & 3) * 2;
            float h_[4];
#pragma unroll
            for (int j = 0; j < 4; j++) {
                const float ig = sigf(acc[si][0][j]);
                const float fg = sigf(acc[si][1][j]);
                const float gt = tanhfast(acc[si][2][j]);
                const float og = sigf(acc[si][3][j]);
                const float cn = fmaf(fg, c_[si * 4 + j], ig * gt);
                c_[si * 4 + j] = cn;
                h_[j] = og * tanhfast(cn);
            }
            *(__half2*)&At[ra * PH + u0]       = __floats2half2_rn(h_[0], h_[1]);
            *(__half2*)&At[(ra + 8) * PH + u0] = __floats2half2_rn(h_[2], h_[3]);
        }

        // stage x(t+1)
        if (tid < 96 && (t + 1) < T_)
            At[(tid & 31) * PH + 64 + (tid >> 5)] = __float2half_rn(xr);

        __syncthreads();   // h(t) + x(t+1) visible
    }

    // epilogue: decode h(T-1)
    if (tid < 96) {
        const int o = tid >> 5, r = tid & 31;
        const uint32_t* hrow = (const uint32_t*)(At + r * PH);
        float dsum = bdv;
#pragma unroll 8
        for (int k2 = 0; k2 < 32; k2++) {
            const float2 hv = __half22float2(*(const __half2*)&hrow[k2]);
            dsum = fmaf(hv.x, wdecs[o * 64 + 2 * k2],     dsum);
            dsum = fmaf(hv.y, wdecs[o * 64 + 2 * k2 + 1], dsum);
        }
        out[((size_t)(row0 + r) * T_ + (T_ - 1)) * 3 + o] = dsum;
    }
}

extern "C" void kernel_launch(void* const* d_in, const int* in_sizes, int n_in,
                              void* d_out, int out_size) {
    const float* x    = (const float*)d_in[0];
    const float* Wih  = (const float*)d_in[1];
    const float* Whh  = (const float*)d_in[2];
    const float* bih  = (const float*)d_in[3];
    const float* bhh  = (const float*)d_in[4];
    const float* Wdec = (const float*)d_in[5];
    const float* bdec = (const float*)d_in[6];
    float* out = (float*)d_out;

    lstm_hmma_kernel<<<B_ / RT, NT>>>(x, Wih, Whh, bih, bhh, Wdec, bdec, out);
}

// round 15
// speedup vs baseline: 4.4347x; 1.0216x over previous
#include <cuda_runtime.h>
#include <cuda_fp16.h>
#include <cstdint>

// LSTMAnomalyDetector: B=4096, T=512, I=3, H=64 (PyTorch gate order i,f,g,o)
//
// Round-15: HMMA (mma.sync.m16n8k16 fp16->fp32), grid=128 CTAs x 512 threads,
// 32 rows/CTA persistent. 16 warps: warp = (M-tile mt, N-set s); per warp
// 4 gate-tiles x 5 K-tiles = 20 HMMA/step. B=[Whh|Wih|bias] in registers
// (40 regs). A=[h|x|1] fp16 DOUBLE-BUFFERED smem tile -> ONE barrier/step.
// Nonlinearities in-register (gate-aligned N tiles), c fp32 in regs.
// Decode done SIMT by threads<96 in phase 1, overlapped with frag loads.

#define B_    4096
#define T_    512
#define RT    32          // rows per CTA
#define NT    512
#define PH    88          // A-tile pitch in halfs (176B)
#define PHB   176

__device__ __forceinline__ float tanhfast(float v) {
    float y; asm("tanh.approx.f32 %0, %1;" : "=f"(y) : "f"(v)); return y;
}
__device__ __forceinline__ float sigf(float v) {
    return fmaf(0.5f, tanhfast(0.5f * v), 0.5f);
}
__device__ __forceinline__ uint32_t smem_u32(const void* p) {
    uint32_t a;
    asm("{ .reg .u64 t; cvta.to.shared.u64 t, %1; cvt.u32.u64 %0, t; }" : "=r"(a) : "l"(p));
    return a;
}
__device__ __forceinline__ uint32_t h2u(float a, float b) {
    __half2 h = __floats2half2_rn(a, b);
    return *(uint32_t*)&h;
}
__device__ __forceinline__ void ldm4(uint32_t* r, uint32_t addr) {
    asm volatile("ldmatrix.sync.aligned.m8n8.x4.shared.b16 {%0,%1,%2,%3}, [%4];"
                 : "=r"(r[0]), "=r"(r[1]), "=r"(r[2]), "=r"(r[3]) : "r"(addr));
}
__device__ __forceinline__ void mma_z(float* d, const uint32_t* a, const uint32_t* b) {
    const float z = 0.0f;
    asm volatile("mma.sync.aligned.m16n8k16.row.col.f32.f16.f16.f32 "
                 "{%0,%1,%2,%3}, {%4,%5,%6,%7}, {%8,%9}, {%10,%10,%10,%10};"
                 : "=f"(d[0]), "=f"(d[1]), "=f"(d[2]), "=f"(d[3])
                 : "r"(a[0]), "r"(a[1]), "r"(a[2]), "r"(a[3]),
                   "r"(b[0]), "r"(b[1]), "f"(z));
}
__device__ __forceinline__ void mma_acc(float* d, const uint32_t* a, const uint32_t* b) {
    asm volatile("mma.sync.aligned.m16n8k16.row.col.f32.f16.f16.f32 "
                 "{%0,%1,%2,%3}, {%4,%5,%6,%7}, {%8,%9}, {%0,%1,%2,%3};"
                 : "+f"(d[0]), "+f"(d[1]), "+f"(d[2]), "+f"(d[3])
                 : "r"(a[0]), "r"(a[1]), "r"(a[2]), "r"(a[3]),
                   "r"(b[0]), "r"(b[1]));
}

__global__ void __launch_bounds__(NT)
lstm_hmma_kernel(const float* __restrict__ x,      // [B, T, 3]
                 const float* __restrict__ Wih,    // [256, 3]
                 const float* __restrict__ Whh,    // [256, 64]
                 const float* __restrict__ bih,    // [256]
                 const float* __restrict__ bhh,    // [256]
                 const float* __restrict__ Wdec,   // [3, 64]
                 const float* __restrict__ bdec,   // [3]
                 float* __restrict__ out)          // [B, T, 3]
{
    __shared__ __align__(16) __half At[2][RT * PH];  // [buf][row][col]: 0-63 h, 64-66 x, 67=1, 68+ pad
    __shared__ float wdecs[3 * 64];

    const int tid  = threadIdx.x;
    const int wid  = tid >> 5;
    const int lane = tid & 31;
    const int row0 = blockIdx.x * RT;
    const int mt   = wid >> 3;     // M-tile: rows 16mt..16mt+15
    const int s    = wid & 7;      // N set: units 8s..8s+7 of each gate

    // ---- setup -----------------------------------------------------------
    for (int i = tid; i < 2 * RT * (PH / 2); i += NT) ((uint32_t*)At)[i] = 0u;
    for (int i = tid; i < 192; i += NT) wdecs[i] = Wdec[i];
    __syncthreads();
    if (tid < 96) {   // x(0) -> buffer 0
        const int o = tid >> 5, r = tid & 31;
        At[0][r * PH + 64 + o] = __float2half_rn(x[((size_t)(row0 + r) * T_) * 3 + o]);
    }
    if (tid < RT) {   // constant-1 column in BOTH buffers
        At[0][tid * PH + 67] = __float2half_rn(1.0f);
        At[1][tid * PH + 67] = __float2half_rn(1.0f);
    }

    // B fragments in registers: [gate][ktile][2]; col = 64g + 8s + lane/4
    uint32_t bF[4][5][2];
#pragma unroll
    for (int g = 0; g < 4; g++) {
        const int col = 64 * g + 8 * s + (lane >> 2);
        const int kq  = (lane & 3) * 2;
#pragma unroll
        for (int kt = 0; kt < 4; kt++) {
            const int k0 = 16 * kt + kq;
            bF[g][kt][0] = h2u(Whh[col * 64 + k0],     Whh[col * 64 + k0 + 1]);
            bF[g][kt][1] = h2u(Whh[col * 64 + k0 + 8], Whh[col * 64 + k0 + 9]);
        }
        float va = 0.f, vb = 0.f;   // ktile 4: rows 64-66 = Wih, 67 = bias, rest 0
        if (kq == 0)      { va = Wih[col * 3 + 0]; vb = Wih[col * 3 + 1]; }
        else if (kq == 2) { va = Wih[col * 3 + 2]; vb = bih[col] + bhh[col]; }
        bF[g][4][0] = h2u(va, vb);
        bF[g][4][1] = 0u;
    }

    float c_[4];
#pragma unroll
    for (int j = 0; j < 4; j++) c_[j] = 0.0f;

    float bdv = 0.0f;
    if (tid < 96) bdv = bdec[tid >> 5];

    // ldmatrix lane addresses for both buffers (ktile via +32B)
    const uint32_t arow = (uint32_t)((16 * mt + (lane & 7) + ((lane >> 3) & 1) * 8) * PHB)
                        + (uint32_t)(((lane >> 4) & 1) * 16);
    const uint32_t ab0 = smem_u32(&At[0][0]) + arow;
    const uint32_t ab1 = smem_u32(&At[1][0]) + arow;

    // nonlinearity / writeback coordinates
    const int ra = 16 * mt + (lane >> 2);       // row a (row b = ra+8)
    const int u0 = 8 * s + (lane & 3) * 2;      // unit pair base

    __syncthreads();

    // ---- timestep loop -----------------------------------------------------
    for (int t = 0; t < T_; t++) {
        const int cur = t & 1, nxt = cur ^ 1;
        const uint32_t abase = cur ? ab1 : ab0;

        // phase 1: A fragments; decode h(t-1); prefetch x(t+1)
        uint32_t aF[5][4];
#pragma unroll
        for (int kt = 0; kt < 5; kt++) ldm4(aF[kt], abase + 32u * kt);

        float xr = 0.0f;
        if (tid < 96) {
            const int o = tid >> 5, r = tid & 31;
            if (t + 1 < T_)
                xr = x[((size_t)(row0 + r) * T_ + (t + 1)) * 3 + o];
            if (t > 0) {
                const uint32_t* hrow = (const uint32_t*)(&At[cur][r * PH]);
                float dsum = bdv;
#pragma unroll 8
                for (int k2 = 0; k2 < 32; k2++) {
                    const float2 hv = __half22float2(*(const __half2*)&hrow[k2]);
                    dsum = fmaf(hv.x, wdecs[o * 64 + 2 * k2],     dsum);
                    dsum = fmaf(hv.y, wdecs[o * 64 + 2 * k2 + 1], dsum);
                }
                out[((size_t)(row0 + r) * T_ + (t - 1)) * 3 + o] = dsum;
            }
        }

        // phase 2: HMMA (4 independent 5-chains)
        float acc[4][4];
#pragma unroll
        for (int g = 0; g < 4; g++) {
            mma_z(acc[g], aF[0], bF[g][0]);
#pragma unroll
            for (int kt = 1; kt < 5; kt++)
                mma_acc(acc[g], aF[kt], bF[g][kt]);
        }

        // phase 3: nonlinearities + h writeback into buf[nxt]
        // acc[g][j]: j=0 (ra,u0) j=1 (ra,u0+1) j=2 (ra+8,u0) j=3 (ra+8,u0+1)
        float h_[4];
#pragma unroll
        for (int j = 0; j < 4; j++) {
            const float ig = sigf(acc[0][j]);
            const float fg = sigf(acc[1][j]);
            const float gt = tanhfast(acc[2][j]);
            const float og = sigf(acc[3][j]);
            const float cn = fmaf(fg, c_[j], ig * gt);
            c_[j] = cn;
            h_[j] = og * tanhfast(cn);
        }
        *(__half2*)&At[nxt][ra * PH + u0]       = __floats2half2_rn(h_[0], h_[1]);
        *(__half2*)&At[nxt][(ra + 8) * PH + u0] = __floats2half2_rn(h_[2], h_[3]);

        // stage x(t+1) into buf[nxt]
        if (tid < 96 && (t + 1) < T_)
            At[nxt][(tid & 31) * PH + 64 + (tid >> 5)] = __float2half_rn(xr);

        __syncthreads();   // single barrier: buf[nxt] complete for step t+1
    }

    // epilogue: decode h(T-1) (written into buffer (T_)&1 = 0)
    if (tid < 96) {
        const int o = tid >> 5, r = tid & 31;
        const uint32_t* hrow = (const uint32_t*)(&At[0][r * PH]);
        float dsum = bdv;
#pragma unroll 8
        for (int k2 = 0; k2 < 32; k2++) {
            const float2 hv = __half22float2(*(const __half2*)&hrow[k2]);
            dsum = fmaf(hv.x, wdecs[o * 64 + 2 * k2],     dsum);
            dsum = fmaf(hv.y, wdecs[o * 64 + 2 * k2 + 1], dsum);
        }
        out[((size_t)(row0 + r) * T_ + (T_ - 1)) * 3 + o] = dsum;
    }
}

extern "C" void kernel_launch(void* const* d_in, const int* in_sizes, int n_in,
                              void* d_out, int out_size) {
    const float* x    = (const float*)d_in[0];
    const float* Wih  = (const float*)d_in[1];
    const float* Whh  = (const float*)d_in[2];
    const float* bih  = (const float*)d_in[3];
    const float* bhh  = (const float*)d_in[4];
    const float* Wdec = (const float*)d_in[5];
    const float* bdec = (const float*)d_in[6];
    float* out = (float*)d_out;

    lstm_hmma_kernel<<<B_ / RT, NT>>>(x, Wih, Whh, bih, bhh, Wdec, bdec, out);
}